// round 15
// baseline (speedup 1.0000x reference)
#include <cuda_runtime.h>
#include <cuda_fp16.h>
#include <cstdint>

#define N_PTS  400000
#define G_SEG  30000
#define C_IN   64
#define C_OUT  128
#define EPSV   1e-3f

typedef unsigned long long ull;

// ---------------- static device scratch (no runtime allocation) ----------------
__device__ __half g_y[(size_t)N_PTS * C_OUT];    // 102.4 MB  post-GEMM (pre-BN1) activations, fp16
__device__ __half g_Wt[C_OUT * C_IN];            // W transposed [n][k], fp16
__device__ float g_seg[(size_t)G_SEG * C_OUT];   // 15.36 MB  segment sums s_g
__device__ int   g_hist[G_SEG];
__device__ int   g_off[G_SEG];
__device__ int   g_cursor[G_SEG];
__device__ int   g_order[N_PTS];
__device__ int   g_total;
__device__ float g_bn1_sum[C_OUT], g_bn1_sq[C_OUT];
__device__ float g_bn2_sum[C_OUT], g_bn2_sq[C_OUT];

// ---------------- float4 helpers ----------------
__device__ __forceinline__ float4 f4add(float4 a, float4 b){ return make_float4(a.x+b.x, a.y+b.y, a.z+b.z, a.w+b.w); }
__device__ __forceinline__ float4 f4sub(float4 a, float4 b){ return make_float4(a.x-b.x, a.y-b.y, a.z-b.z, a.w-b.w); }
__device__ __forceinline__ float4 f4mul(float4 a, float4 b){ return make_float4(a.x*b.x, a.y*b.y, a.z*b.z, a.w*b.w); }
__device__ __forceinline__ float4 f4smul(float s, float4 a){ return make_float4(s*a.x, s*a.y, s*a.z, s*a.w); }
__device__ __forceinline__ float4 f4fma(float4 a, float4 b, float4 c){
    return make_float4(fmaf(a.x,b.x,c.x), fmaf(a.y,b.y,c.y), fmaf(a.z,b.z,c.z), fmaf(a.w,b.w,c.w));
}
__device__ __forceinline__ float4 f4sfma(float s, float4 a, float4 c){
    return make_float4(fmaf(s,a.x,c.x), fmaf(s,a.y,c.y), fmaf(s,a.z,c.z), fmaf(s,a.w,c.w));
}
__device__ __forceinline__ float4 f4zero(){ return make_float4(0.f,0.f,0.f,0.f); }

// load 4 channels (8 bytes fp16) as float4 — normal and evict-first variants
__device__ __forceinline__ float4 h4_to_f4(uint2 raw) {
    __half2 h0 = *(__half2*)&raw.x;
    __half2 h1 = *(__half2*)&raw.y;
    float2 f0 = __half22float2(h0);
    float2 f1 = __half22float2(h1);
    return make_float4(f0.x, f0.y, f1.x, f1.y);
}
__device__ __forceinline__ float4 ldy4(const __half* p)    { return h4_to_f4(*(const uint2*)p); }
__device__ __forceinline__ float4 ldy4_cs(const __half* p) { return h4_to_f4(__ldcs((const uint2*)p)); }

// per-lane BN affine (4 channels) from raw sums: a = g*rsqrt(var+eps), b = be - m*a
__device__ __forceinline__ void bn_affine(const float* sum, const float* sq,
                                          const float* gm, const float* be,
                                          int c, float inv_n, float4& a, float4& b)
{
    float4 s  = *(const float4*)(sum + c);
    float4 q  = *(const float4*)(sq  + c);
    float4 gg = __ldg((const float4*)(gm + c));
    float4 bb = __ldg((const float4*)(be + c));
    float mx = s.x * inv_n, my = s.y * inv_n, mz = s.z * inv_n, mw = s.w * inv_n;
    a.x = gg.x * rsqrtf(q.x * inv_n - mx*mx + EPSV);
    a.y = gg.y * rsqrtf(q.y * inv_n - my*my + EPSV);
    a.z = gg.z * rsqrtf(q.z * inv_n - mz*mz + EPSV);
    a.w = gg.w * rsqrtf(q.w * inv_n - mw*mw + EPSV);
    b.x = bb.x - mx * a.x;  b.y = bb.y - my * a.y;
    b.z = bb.z - mz * a.z;  b.w = bb.w - mw * a.w;
}

// ---------------- K0: zero small state + transpose W -> fp16 ----------------
__global__ void k_init(const float* __restrict__ W) {
    int i = blockIdx.x * blockDim.x + threadIdx.x;
    if (i < G_SEG) g_hist[i] = 0;
    if (i == 0) g_total = 0;
    if (i < C_OUT) { g_bn1_sum[i]=0.f; g_bn1_sq[i]=0.f; g_bn2_sum[i]=0.f; g_bn2_sq[i]=0.f; }
    if (i < C_IN * C_OUT) {
        int k = i >> 7, nn = i & 127;
        g_Wt[nn * C_IN + k] = __float2half(W[i]);
    }
}

// ---------------- K-hist ----------------
__global__ void k_hist(const int* __restrict__ unq, int n) {
    int i = blockIdx.x * blockDim.x + threadIdx.x;
    if (i < n) atomicAdd(&g_hist[unq[i]], 1);
}

// ---------------- K-offsets: unordered CSR offsets via block scan + atomic base ----------------
__global__ __launch_bounds__(256) void k_offsets() {
    int tid = threadIdx.x;
    int g = blockIdx.x * 256 + tid;
    int c = (g < G_SEG) ? g_hist[g] : 0;
    int lane = tid & 31, wid = tid >> 5;

    int x = c;
    #pragma unroll
    for (int d = 1; d < 32; d <<= 1) {
        int y = __shfl_up_sync(0xffffffffu, x, d);
        if (lane >= d) x += y;
    }
    __shared__ int ws[8];
    __shared__ int bbase;
    if (lane == 31) ws[wid] = x;
    __syncthreads();
    if (wid == 0 && lane < 8) {
        int v = ws[lane];
        #pragma unroll
        for (int d = 1; d < 8; d <<= 1) {
            int y = __shfl_up_sync(0xffu, v, d);
            if (lane >= d) v += y;
        }
        ws[lane] = v;
        if (lane == 7) bbase = atomicAdd(&g_total, v);
    }
    __syncthreads();
    int off = bbase + (x - c) + (wid ? ws[wid-1] : 0);
    if (g < G_SEG) { g_off[g] = off; g_cursor[g] = off; }
}

// ---------------- K3: scatter point indices into CSR order ----------------
__global__ void k_scatter(const int* __restrict__ unq, int n) {
    int i = blockIdx.x * blockDim.x + threadIdx.x;
    if (i < n) {
        int g = unq[i];
        int p = atomicAdd(&g_cursor[g], 1);
        g_order[p] = i;
    }
}

// ---------------- K1: tensor-core GEMM, 8 tiles/block, double-buffered A ----------------
#define PITCH 72   // halves per smem row; fragment LDS conflict-free
#define K1_TILES 8
__global__ __launch_bounds__(256) void k1_mma(
    const float* __restrict__ A, const float* __restrict__ bias, int n)
{
    __shared__ __half As[2][64 * PITCH]; // 2 x 9216 B (double buffer)
    __shared__ __half Ws[128 * PITCH];   // 18432 B (Wt[n][k] layout)
    __shared__ float bn_s[C_OUT], bn_q[C_OUT];

    int tid = threadIdx.x;

    if (tid < C_OUT) { bn_s[tid] = 0.f; bn_q[tid] = 0.f; }

    // load pre-transposed Wt once: 1024 uint4, 4/thread. Conflict-free STS.128.
    #pragma unroll
    for (int it = 0; it < 4; it++) {
        int flat = it * 256 + tid;
        int row = flat >> 3;             // 8 uint4 per 64-half row
        int c8  = flat & 7;
        *(uint4*)&Ws[row * PITCH + c8 * 8] = ((const uint4*)g_Wt)[flat];
    }

    // per-thread A-load geometry: 4 float4/tile (row r = flat>>4, col c4 = flat&15)
    int lrow[4], lc4[4];
    #pragma unroll
    for (int it = 0; it < 4; it++) {
        int flat = it * 256 + tid;
        lrow[it] = flat >> 4;
        lc4[it]  = flat & 15;
    }

    // prologue: load tile 0 into As[0]
    uint2 stage[4];
    {
        int m0 = blockIdx.x * K1_TILES * 64;
        #pragma unroll
        for (int it = 0; it < 4; it++) {
            float4 v = make_float4(0.f,0.f,0.f,0.f);
            if (m0 + lrow[it] < n)
                v = __ldcs((const float4*)(A + (size_t)(m0 + lrow[it]) * C_IN + lc4[it] * 4));
            __half2 h0 = __floats2half2_rn(v.x, v.y);
            __half2 h1 = __floats2half2_rn(v.z, v.w);
            stage[it] = make_uint2(*(uint32_t*)&h0, *(uint32_t*)&h1);
        }
        #pragma unroll
        for (int it = 0; it < 4; it++)
            *(uint2*)&As[0][lrow[it] * PITCH + lc4[it] * 4] = stage[it];
    }
    __syncthreads();

    int lane = tid & 31, w = tid >> 5;
    int g   = lane >> 2;                 // 0..7
    int tig = lane & 3;                  // 0..3
    int wm = (w & 1) * 32;               // warp m offset (2 warps over 64 rows)
    int wn = (w >> 1) * 32;              // warp n offset (4 warps over 128 cols)

    float2 bv[4];
    #pragma unroll
    for (int nt = 0; nt < 4; nt++) {
        int c = wn + nt * 8 + 2 * tig;
        bv[nt] = make_float2(__ldg(bias + c), __ldg(bias + c + 1));
    }
    float ps[4][2], pq[4][2];
    #pragma unroll
    for (int nt = 0; nt < 4; nt++) { ps[nt][0]=0.f; ps[nt][1]=0.f; pq[nt][0]=0.f; pq[nt][1]=0.f; }

    #pragma unroll
    for (int t = 0; t < K1_TILES; t++) {
        int buf = t & 1;
        int m0 = (blockIdx.x * K1_TILES + t) * 64;

        // prefetch tile t+1 into regs (LDG issued before MMAs consume As[buf])
        if (t + 1 < K1_TILES) {
            int m1 = m0 + 64;
            #pragma unroll
            for (int it = 0; it < 4; it++) {
                float4 v = make_float4(0.f,0.f,0.f,0.f);
                if (m1 + lrow[it] < n)
                    v = __ldcs((const float4*)(A + (size_t)(m1 + lrow[it]) * C_IN + lc4[it] * 4));
                __half2 h0 = __floats2half2_rn(v.x, v.y);
                __half2 h1 = __floats2half2_rn(v.z, v.w);
                stage[it] = make_uint2(*(uint32_t*)&h0, *(uint32_t*)&h1);
            }
        }

        float d[2][4][4];
        #pragma unroll
        for (int mt = 0; mt < 2; mt++)
            #pragma unroll
            for (int nt = 0; nt < 4; nt++)
                #pragma unroll
                for (int i = 0; i < 4; i++) d[mt][nt][i] = 0.f;

        #pragma unroll
        for (int kt = 0; kt < 4; kt++) {
            int k0 = kt * 16;
            uint32_t a[2][4];
            #pragma unroll
            for (int mt = 0; mt < 2; mt++) {
                int mb = wm + mt * 16;
                a[mt][0] = *(uint32_t*)&As[buf][(mb + g)     * PITCH + k0 + 2 * tig];
                a[mt][1] = *(uint32_t*)&As[buf][(mb + g + 8) * PITCH + k0 + 2 * tig];
                a[mt][2] = *(uint32_t*)&As[buf][(mb + g)     * PITCH + k0 + 2 * tig + 8];
                a[mt][3] = *(uint32_t*)&As[buf][(mb + g + 8) * PITCH + k0 + 2 * tig + 8];
            }
            uint32_t b[4][2];
            #pragma unroll
            for (int nt = 0; nt < 4; nt++) {
                int nb = wn + nt * 8 + g;
                b[nt][0] = *(uint32_t*)&Ws[nb * PITCH + k0 + 2 * tig];
                b[nt][1] = *(uint32_t*)&Ws[nb * PITCH + k0 + 2 * tig + 8];
            }
            #pragma unroll
            for (int mt = 0; mt < 2; mt++)
                #pragma unroll
                for (int nt = 0; nt < 4; nt++)
                    asm volatile(
                        "mma.sync.aligned.m16n8k16.row.col.f32.f16.f16.f32 "
                        "{%0,%1,%2,%3}, {%4,%5,%6,%7}, {%8,%9}, {%0,%1,%2,%3};"
                        : "+f"(d[mt][nt][0]), "+f"(d[mt][nt][1]),
                          "+f"(d[mt][nt][2]), "+f"(d[mt][nt][3])
                        : "r"(a[mt][0]), "r"(a[mt][1]), "r"(a[mt][2]), "r"(a[mt][3]),
                          "r"(b[nt][0]), "r"(b[nt][1]));
        }

        // store prefetched tile into the other buffer (safe: its readers synced at end of t-1)
        if (t + 1 < K1_TILES) {
            #pragma unroll
            for (int it = 0; it < 4; it++)
                *(uint2*)&As[1 - buf][lrow[it] * PITCH + lc4[it] * 4] = stage[it];
        }

        // epilogue: +bias, fp16 store, BN1 stats on rounded values
        #pragma unroll
        for (int mt = 0; mt < 2; mt++) {
            #pragma unroll
            for (int rh = 0; rh < 2; rh++) {
                int row = m0 + wm + mt * 16 + g + rh * 8;
                if (row < n) {
                    #pragma unroll
                    for (int nt = 0; nt < 4; nt++) {
                        float v0 = d[mt][nt][rh * 2 + 0] + bv[nt].x;
                        float v1 = d[mt][nt][rh * 2 + 1] + bv[nt].y;
                        __half2 h = __floats2half2_rn(v0, v1);
                        int c = wn + nt * 8 + 2 * tig;
                        *(uint32_t*)(g_y + (size_t)row * C_OUT + c) = *(uint32_t*)&h;
                        float2 f = __half22float2(h);
                        ps[nt][0] += f.x; pq[nt][0] += f.x * f.x;
                        ps[nt][1] += f.y; pq[nt][1] += f.y * f.y;
                    }
                }
            }
        }
        __syncthreads();   // readers of As[buf] done; As[1-buf] fully written
    }

    // reduce across g (lane bits 2..4) so only tig lanes carry channel sums
    #pragma unroll
    for (int m = 4; m <= 16; m <<= 1) {
        #pragma unroll
        for (int nt = 0; nt < 4; nt++) {
            ps[nt][0] += __shfl_xor_sync(0xffffffffu, ps[nt][0], m);
            ps[nt][1] += __shfl_xor_sync(0xffffffffu, ps[nt][1], m);
            pq[nt][0] += __shfl_xor_sync(0xffffffffu, pq[nt][0], m);
            pq[nt][1] += __shfl_xor_sync(0xffffffffu, pq[nt][1], m);
        }
    }
    if (g == 0) {
        #pragma unroll
        for (int nt = 0; nt < 4; nt++) {
            int c = wn + nt * 8 + 2 * tig;
            atomicAdd(&bn_s[c],     ps[nt][0]);
            atomicAdd(&bn_s[c + 1], ps[nt][1]);
            atomicAdd(&bn_q[c],     pq[nt][0]);
            atomicAdd(&bn_q[c + 1], pq[nt][1]);
        }
    }
    __syncthreads();
    if (tid < C_OUT) {
        atomicAdd(&g_bn1_sum[tid], bn_s[tid]);
        atomicAdd(&g_bn1_sq[tid],  bn_q[tid]);
    }
}

// ---------------- K4: gather segment-sum (grid-stride warp loop) + analytic BN2 stats ----------------
#define K4_GRP_PER_WARP 4
__global__ __launch_bounds__(128) void k4_segsum(
    const float* __restrict__ P,
    const float* __restrict__ Wp1, const float* __restrict__ bp1,
    const float* __restrict__ Wp2, const float* __restrict__ bp2,
    const float* __restrict__ g1,  const float* __restrict__ be1, int n)
{
    int tid = threadIdx.x, lane = tid & 31, w = tid >> 5;
    int warpId = blockIdx.x * 4 + w;
    int nwarp = gridDim.x * 4;

    const float4* W1 = (const float4*)Wp1;
    const float4* W2 = (const float4*)Wp2;
    float4 w10 = __ldg(W1 + lane),      w11 = __ldg(W1 + 32 + lane), w12 = __ldg(W1 + 64 + lane);
    float4 b1v = __ldg((const float4*)bp1 + lane);
    float4 w20 = __ldg(W2 + lane),      w21 = __ldg(W2 + 32 + lane), w22 = __ldg(W2 + 64 + lane);
    float4 b2v = __ldg((const float4*)bp2 + lane);
    float4 a1, bb1;
    bn_affine(g_bn1_sum, g_bn1_sq, g1, be1, lane * 4, 1.0f / (float)n, a1, bb1);

    float4 accS = f4zero(), accQ = f4zero();   // BN2 sum / sumsq partials

    for (int g = warpId; g < G_SEG; g += nwarp) {
        int beg = g_off[g];
        int cnt = g_hist[g];
        float4 s = f4zero(), tA = f4zero(), tQ = f4zero();

        int iA = (cnt > 0) ? __ldg(&g_order[beg]) : 0;
        for (int m = 0; m < cnt; m++) {
            int iB = (m + 1 < cnt) ? __ldg(&g_order[beg + m + 1]) : 0;
            float px = floorf(__ldg(P + 3*iA));
            float py = floorf(__ldg(P + 3*iA + 1));
            float pz = floorf(__ldg(P + 3*iA + 2));
            float4 y = ldy4(g_y + (size_t)iA * C_OUT + lane*4);   // default: keep L2-resident for k5
            float4 feat = f4fma(y, a1, bb1);
            float4 pw1 = f4sfma(px, w10, f4sfma(py, w11, f4sfma(pz, w12, b1v)));
            float4 pw2 = f4sfma(px, w20, f4sfma(py, w21, f4sfma(pz, w22, b2v)));
            float4 a = f4mul(pw2, feat);
            s  = f4fma(pw1, feat, s);
            tA = f4add(tA, a);
            tQ = f4fma(a, a, tQ);
            iA = iB;
        }
        *(float4*)(g_seg + (size_t)g * C_OUT + lane*4) = s;

        float c = (float)cnt;
        accS = f4add(accS, f4sub(tA, f4smul(c, s)));
        float4 q = f4sub(tQ, f4smul(2.f, f4mul(s, tA)));
        q = f4fma(s, f4smul(c, s), q);
        accQ = f4add(accQ, q);
    }

    __shared__ float rs[512], rq[512];
    rs[w*128 + lane*4 + 0] = accS.x; rq[w*128 + lane*4 + 0] = accQ.x;
    rs[w*128 + lane*4 + 1] = accS.y; rq[w*128 + lane*4 + 1] = accQ.y;
    rs[w*128 + lane*4 + 2] = accS.z; rq[w*128 + lane*4 + 2] = accQ.z;
    rs[w*128 + lane*4 + 3] = accS.w; rq[w*128 + lane*4 + 3] = accQ.w;
    __syncthreads();
    if (tid < 128) {
        float s = 0.f, q = 0.f;
        #pragma unroll
        for (int t = 0; t < 4; t++) { s += rs[t*128 + tid]; q += rq[t*128 + tid]; }
        atomicAdd(&g_bn2_sum[tid], s);
        atomicAdd(&g_bn2_sq[tid], q);
    }
}

// ---------------- K5: final output (grid-stride warp loop; streaming hints) ----------------
__global__ __launch_bounds__(256) void k5_out(
    const float* __restrict__ P, const int* __restrict__ unq,
    const float* __restrict__ Wp2, const float* __restrict__ bp2,
    const float* __restrict__ g1,  const float* __restrict__ be1,
    const float* __restrict__ g2,  const float* __restrict__ be2,
    float* __restrict__ Out, int n)
{
    int lane = threadIdx.x & 31;
    int warpId = (blockIdx.x * blockDim.x + threadIdx.x) >> 5;
    int nwarp = (gridDim.x * blockDim.x) >> 5;

    float inv_n = 1.0f / (float)n;
    float4 a1, bb1, a2, bb2;
    bn_affine(g_bn1_sum, g_bn1_sq, g1, be1, lane * 4, inv_n, a1, bb1);
    bn_affine(g_bn2_sum, g_bn2_sq, g2, be2, lane * 4, inv_n, a2, bb2);
    const float4* W2 = (const float4*)Wp2;
    float4 w20 = __ldg(W2 + lane), w21 = __ldg(W2 + 32 + lane), w22 = __ldg(W2 + 64 + lane);
    float4 b2v = __ldg((const float4*)bp2 + lane);

    for (int i = warpId; i < n; i += nwarp) {
        int g = __ldg(unq + i);
        float px = floorf(__ldg(P + 3*i));
        float py = floorf(__ldg(P + 3*i + 1));
        float pz = floorf(__ldg(P + 3*i + 2));
        float4 y  = ldy4_cs(g_y + (size_t)i * C_OUT + lane*4);          // last read: evict-first
        float4 sv = *(const float4*)(g_seg + (size_t)g * C_OUT + lane*4); // keep L2-resident
        float4 feat = f4fma(y, a1, bb1);
        float4 pw2 = f4sfma(px, w20, f4sfma(py, w21, f4sfma(pz, w22, b2v)));
        float4 o = f4sub(f4mul(pw2, feat), sv);
        o = f4fma(o, a2, bb2);
        o.x = fmaxf(o.x, 0.f); o.y = fmaxf(o.y, 0.f);
        o.z = fmaxf(o.z, 0.f); o.w = fmaxf(o.w, 0.f);
        __stcs((float4*)(Out + (size_t)i * C_OUT + lane*4), o);          // evict-first store
    }
}

// ---------------- launch ----------------
extern "C" void kernel_launch(void* const* d_in, const int* in_sizes, int n_in,
                              void* d_out, int out_size)
{
    const float* P    = (const float*)d_in[0];   // points_xyz [N,3]
    const float* X    = (const float*)d_in[1];   // feat_all  [N,64]
    const int*   unq  = (const int*)  d_in[2];   // unq_inv   [N]
    const float* Wpre = (const float*)d_in[3];   // [64,128]
    const float* bpre = (const float*)d_in[4];
    const float* g1   = (const float*)d_in[5];
    const float* be1  = (const float*)d_in[6];
    const float* Wp1  = (const float*)d_in[7];   // [3,128]
    const float* bp1  = (const float*)d_in[8];
    const float* Wp2  = (const float*)d_in[9];   // [3,128]
    const float* bp2  = (const float*)d_in[10];
    const float* g2   = (const float*)d_in[11];
    const float* be2  = (const float*)d_in[12];
    float* Out = (float*)d_out;

    int N = in_sizes[2];

    // fork/join: CSR chain overlaps with k1 GEMM.
    cudaStream_t s2;
    cudaEvent_t evFork, evJoin;
    cudaStreamCreateWithFlags(&s2, cudaStreamNonBlocking);
    cudaEventCreateWithFlags(&evFork, cudaEventDisableTiming);
    cudaEventCreateWithFlags(&evJoin, cudaEventDisableTiming);

    k_init<<<(G_SEG + 255) / 256, 256>>>(Wpre);
    cudaEventRecord(evFork, 0);
    cudaStreamWaitEvent(s2, evFork, 0);

    // stream B: CSR chain (only depends on unq + init)
    k_hist<<<(N + 255) / 256, 256, 0, s2>>>(unq, N);
    k_offsets<<<(G_SEG + 255) / 256, 256, 0, s2>>>();
    k_scatter<<<(N + 255) / 256, 256, 0, s2>>>(unq, N);
    cudaEventRecord(evJoin, s2);

    // stream A (default): GEMM concurrent with CSR chain (8 tiles/block, double-buffered)
    int rowsPerBlock = 64 * K1_TILES;
    k1_mma<<<(N + rowsPerBlock - 1) / rowsPerBlock, 256>>>(X, bpre, N);

    cudaStreamWaitEvent(0, evJoin, 0);
    k4_segsum<<<G_SEG / (4 * K4_GRP_PER_WARP), 128>>>(P, Wp1, bp1, Wp2, bp2, g1, be1, N);
    k5_out<<<1024, 256>>>(P, unq, Wp2, bp2, g1, be1, g2, be2, Out, N);

    cudaStreamDestroy(s2);
    cudaEventDestroy(evFork);
    cudaEventDestroy(evJoin);
}

// round 16
// speedup vs baseline: 1.0694x; 1.0694x over previous
#include <cuda_runtime.h>
#include <cuda_fp16.h>
#include <cstdint>

#define N_PTS  400000
#define G_SEG  30000
#define C_IN   64
#define C_OUT  128
#define EPSV   1e-3f

typedef unsigned long long ull;

// ---------------- static device scratch (no runtime allocation) ----------------
__device__ __half g_y[(size_t)N_PTS * C_OUT];    // 102.4 MB  post-GEMM (pre-BN1) activations, fp16
__device__ __half g_Wt[C_OUT * C_IN];            // W transposed [n][k], fp16
__device__ float g_seg[(size_t)G_SEG * C_OUT];   // 15.36 MB  segment sums s_g
__device__ int   g_hist[G_SEG];
__device__ int   g_off[G_SEG];
__device__ int   g_cursor[G_SEG];
__device__ int   g_order[N_PTS];
__device__ int   g_total;
__device__ float g_bn1_sum[C_OUT], g_bn1_sq[C_OUT];
__device__ float g_bn2_sum[C_OUT], g_bn2_sq[C_OUT];

// ---------------- float4 helpers ----------------
__device__ __forceinline__ float4 f4add(float4 a, float4 b){ return make_float4(a.x+b.x, a.y+b.y, a.z+b.z, a.w+b.w); }
__device__ __forceinline__ float4 f4sub(float4 a, float4 b){ return make_float4(a.x-b.x, a.y-b.y, a.z-b.z, a.w-b.w); }
__device__ __forceinline__ float4 f4mul(float4 a, float4 b){ return make_float4(a.x*b.x, a.y*b.y, a.z*b.z, a.w*b.w); }
__device__ __forceinline__ float4 f4smul(float s, float4 a){ return make_float4(s*a.x, s*a.y, s*a.z, s*a.w); }
__device__ __forceinline__ float4 f4fma(float4 a, float4 b, float4 c){
    return make_float4(fmaf(a.x,b.x,c.x), fmaf(a.y,b.y,c.y), fmaf(a.z,b.z,c.z), fmaf(a.w,b.w,c.w));
}
__device__ __forceinline__ float4 f4sfma(float s, float4 a, float4 c){
    return make_float4(fmaf(s,a.x,c.x), fmaf(s,a.y,c.y), fmaf(s,a.z,c.z), fmaf(s,a.w,c.w));
}
__device__ __forceinline__ float4 f4zero(){ return make_float4(0.f,0.f,0.f,0.f); }

// load 4 channels (8 bytes fp16) as float4 — normal and evict-first variants
__device__ __forceinline__ float4 h4_to_f4(uint2 raw) {
    __half2 h0 = *(__half2*)&raw.x;
    __half2 h1 = *(__half2*)&raw.y;
    float2 f0 = __half22float2(h0);
    float2 f1 = __half22float2(h1);
    return make_float4(f0.x, f0.y, f1.x, f1.y);
}
__device__ __forceinline__ float4 ldy4(const __half* p)    { return h4_to_f4(*(const uint2*)p); }
__device__ __forceinline__ float4 ldy4_cs(const __half* p) { return h4_to_f4(__ldcs((const uint2*)p)); }

// per-lane BN affine (4 channels) from raw sums: a = g*rsqrt(var+eps), b = be - m*a
__device__ __forceinline__ void bn_affine(const float* sum, const float* sq,
                                          const float* gm, const float* be,
                                          int c, float inv_n, float4& a, float4& b)
{
    float4 s  = *(const float4*)(sum + c);
    float4 q  = *(const float4*)(sq  + c);
    float4 gg = __ldg((const float4*)(gm + c));
    float4 bb = __ldg((const float4*)(be + c));
    float mx = s.x * inv_n, my = s.y * inv_n, mz = s.z * inv_n, mw = s.w * inv_n;
    a.x = gg.x * rsqrtf(q.x * inv_n - mx*mx + EPSV);
    a.y = gg.y * rsqrtf(q.y * inv_n - my*my + EPSV);
    a.z = gg.z * rsqrtf(q.z * inv_n - mz*mz + EPSV);
    a.w = gg.w * rsqrtf(q.w * inv_n - mw*mw + EPSV);
    b.x = bb.x - mx * a.x;  b.y = bb.y - my * a.y;
    b.z = bb.z - mz * a.z;  b.w = bb.w - mw * a.w;
}

// ---------------- K0: zero small state + transpose W -> fp16 ----------------
__global__ void k_init(const float* __restrict__ W) {
    int i = blockIdx.x * blockDim.x + threadIdx.x;
    if (i < G_SEG) g_hist[i] = 0;
    if (i == 0) g_total = 0;
    if (i < C_OUT) { g_bn1_sum[i]=0.f; g_bn1_sq[i]=0.f; g_bn2_sum[i]=0.f; g_bn2_sq[i]=0.f; }
    if (i < C_IN * C_OUT) {
        int k = i >> 7, nn = i & 127;
        g_Wt[nn * C_IN + k] = __float2half(W[i]);
    }
}

// ---------------- K-hist ----------------
__global__ void k_hist(const int* __restrict__ unq, int n) {
    int i = blockIdx.x * blockDim.x + threadIdx.x;
    if (i < n) atomicAdd(&g_hist[unq[i]], 1);
}

// ---------------- K-offsets: unordered CSR offsets via block scan + atomic base ----------------
__global__ __launch_bounds__(256) void k_offsets() {
    int tid = threadIdx.x;
    int g = blockIdx.x * 256 + tid;
    int c = (g < G_SEG) ? g_hist[g] : 0;
    int lane = tid & 31, wid = tid >> 5;

    int x = c;
    #pragma unroll
    for (int d = 1; d < 32; d <<= 1) {
        int y = __shfl_up_sync(0xffffffffu, x, d);
        if (lane >= d) x += y;
    }
    __shared__ int ws[8];
    __shared__ int bbase;
    if (lane == 31) ws[wid] = x;
    __syncthreads();
    if (wid == 0 && lane < 8) {
        int v = ws[lane];
        #pragma unroll
        for (int d = 1; d < 8; d <<= 1) {
            int y = __shfl_up_sync(0xffu, v, d);
            if (lane >= d) v += y;
        }
        ws[lane] = v;
        if (lane == 7) bbase = atomicAdd(&g_total, v);
    }
    __syncthreads();
    int off = bbase + (x - c) + (wid ? ws[wid-1] : 0);
    if (g < G_SEG) { g_off[g] = off; g_cursor[g] = off; }
}

// ---------------- K3: scatter point indices into CSR order ----------------
__global__ void k_scatter(const int* __restrict__ unq, int n) {
    int i = blockIdx.x * blockDim.x + threadIdx.x;
    if (i < n) {
        int g = unq[i];
        int p = atomicAdd(&g_cursor[g], 1);
        g_order[p] = i;
    }
}

// ---------------- K1: tensor-core GEMM, 4 tiles/block, double-buffered A ----------------
#define PITCH 72   // halves per smem row; fragment LDS conflict-free
#define K1_TILES 4
__global__ __launch_bounds__(256) void k1_mma(
    const float* __restrict__ A, const float* __restrict__ bias, int n)
{
    __shared__ __half As[2][64 * PITCH]; // 2 x 9216 B (double buffer)
    __shared__ __half Ws[128 * PITCH];   // 18432 B (Wt[n][k] layout)
    __shared__ float bn_s[C_OUT], bn_q[C_OUT];

    int tid = threadIdx.x;

    if (tid < C_OUT) { bn_s[tid] = 0.f; bn_q[tid] = 0.f; }

    // load pre-transposed Wt once: 1024 uint4, 4/thread. Conflict-free STS.128.
    #pragma unroll
    for (int it = 0; it < 4; it++) {
        int flat = it * 256 + tid;
        int row = flat >> 3;             // 8 uint4 per 64-half row
        int c8  = flat & 7;
        *(uint4*)&Ws[row * PITCH + c8 * 8] = ((const uint4*)g_Wt)[flat];
    }

    // per-thread A-load geometry: 4 float4/tile (row r = flat>>4, col c4 = flat&15)
    int lrow[4], lc4[4];
    #pragma unroll
    for (int it = 0; it < 4; it++) {
        int flat = it * 256 + tid;
        lrow[it] = flat >> 4;
        lc4[it]  = flat & 15;
    }

    // prologue: load tile 0 into As[0]
    uint2 stage[4];
    {
        int m0 = blockIdx.x * K1_TILES * 64;
        #pragma unroll
        for (int it = 0; it < 4; it++) {
            float4 v = make_float4(0.f,0.f,0.f,0.f);
            if (m0 + lrow[it] < n)
                v = __ldcs((const float4*)(A + (size_t)(m0 + lrow[it]) * C_IN + lc4[it] * 4));
            __half2 h0 = __floats2half2_rn(v.x, v.y);
            __half2 h1 = __floats2half2_rn(v.z, v.w);
            stage[it] = make_uint2(*(uint32_t*)&h0, *(uint32_t*)&h1);
        }
        #pragma unroll
        for (int it = 0; it < 4; it++)
            *(uint2*)&As[0][lrow[it] * PITCH + lc4[it] * 4] = stage[it];
    }
    __syncthreads();

    int lane = tid & 31, w = tid >> 5;
    int g   = lane >> 2;                 // 0..7
    int tig = lane & 3;                  // 0..3
    int wm = (w & 1) * 32;               // warp m offset (2 warps over 64 rows)
    int wn = (w >> 1) * 32;              // warp n offset (4 warps over 128 cols)

    float2 bv[4];
    #pragma unroll
    for (int nt = 0; nt < 4; nt++) {
        int c = wn + nt * 8 + 2 * tig;
        bv[nt] = make_float2(__ldg(bias + c), __ldg(bias + c + 1));
    }
    float ps[4][2], pq[4][2];
    #pragma unroll
    for (int nt = 0; nt < 4; nt++) { ps[nt][0]=0.f; ps[nt][1]=0.f; pq[nt][0]=0.f; pq[nt][1]=0.f; }

    #pragma unroll
    for (int t = 0; t < K1_TILES; t++) {
        int buf = t & 1;
        int m0 = (blockIdx.x * K1_TILES + t) * 64;

        // prefetch tile t+1 into regs (LDG issued before MMAs consume As[buf])
        if (t + 1 < K1_TILES) {
            int m1 = m0 + 64;
            #pragma unroll
            for (int it = 0; it < 4; it++) {
                float4 v = make_float4(0.f,0.f,0.f,0.f);
                if (m1 + lrow[it] < n)
                    v = __ldcs((const float4*)(A + (size_t)(m1 + lrow[it]) * C_IN + lc4[it] * 4));
                __half2 h0 = __floats2half2_rn(v.x, v.y);
                __half2 h1 = __floats2half2_rn(v.z, v.w);
                stage[it] = make_uint2(*(uint32_t*)&h0, *(uint32_t*)&h1);
            }
        }

        float d[2][4][4];
        #pragma unroll
        for (int mt = 0; mt < 2; mt++)
            #pragma unroll
            for (int nt = 0; nt < 4; nt++)
                #pragma unroll
                for (int i = 0; i < 4; i++) d[mt][nt][i] = 0.f;

        #pragma unroll
        for (int kt = 0; kt < 4; kt++) {
            int k0 = kt * 16;
            uint32_t a[2][4];
            #pragma unroll
            for (int mt = 0; mt < 2; mt++) {
                int mb = wm + mt * 16;
                a[mt][0] = *(uint32_t*)&As[buf][(mb + g)     * PITCH + k0 + 2 * tig];
                a[mt][1] = *(uint32_t*)&As[buf][(mb + g + 8) * PITCH + k0 + 2 * tig];
                a[mt][2] = *(uint32_t*)&As[buf][(mb + g)     * PITCH + k0 + 2 * tig + 8];
                a[mt][3] = *(uint32_t*)&As[buf][(mb + g + 8) * PITCH + k0 + 2 * tig + 8];
            }
            uint32_t b[4][2];
            #pragma unroll
            for (int nt = 0; nt < 4; nt++) {
                int nb = wn + nt * 8 + g;
                b[nt][0] = *(uint32_t*)&Ws[nb * PITCH + k0 + 2 * tig];
                b[nt][1] = *(uint32_t*)&Ws[nb * PITCH + k0 + 2 * tig + 8];
            }
            #pragma unroll
            for (int mt = 0; mt < 2; mt++)
                #pragma unroll
                for (int nt = 0; nt < 4; nt++)
                    asm volatile(
                        "mma.sync.aligned.m16n8k16.row.col.f32.f16.f16.f32 "
                        "{%0,%1,%2,%3}, {%4,%5,%6,%7}, {%8,%9}, {%0,%1,%2,%3};"
                        : "+f"(d[mt][nt][0]), "+f"(d[mt][nt][1]),
                          "+f"(d[mt][nt][2]), "+f"(d[mt][nt][3])
                        : "r"(a[mt][0]), "r"(a[mt][1]), "r"(a[mt][2]), "r"(a[mt][3]),
                          "r"(b[nt][0]), "r"(b[nt][1]));
        }

        // store prefetched tile into the other buffer (safe: its readers synced at end of t-1)
        if (t + 1 < K1_TILES) {
            #pragma unroll
            for (int it = 0; it < 4; it++)
                *(uint2*)&As[1 - buf][lrow[it] * PITCH + lc4[it] * 4] = stage[it];
        }

        // epilogue: +bias, fp16 store (write-back), BN1 stats on rounded values
        #pragma unroll
        for (int mt = 0; mt < 2; mt++) {
            #pragma unroll
            for (int rh = 0; rh < 2; rh++) {
                int row = m0 + wm + mt * 16 + g + rh * 8;
                if (row < n) {
                    #pragma unroll
                    for (int nt = 0; nt < 4; nt++) {
                        float v0 = d[mt][nt][rh * 2 + 0] + bv[nt].x;
                        float v1 = d[mt][nt][rh * 2 + 1] + bv[nt].y;
                        __half2 h = __floats2half2_rn(v0, v1);
                        int c = wn + nt * 8 + 2 * tig;
                        *(uint32_t*)(g_y + (size_t)row * C_OUT + c) = *(uint32_t*)&h;
                        float2 f = __half22float2(h);
                        ps[nt][0] += f.x; pq[nt][0] += f.x * f.x;
                        ps[nt][1] += f.y; pq[nt][1] += f.y * f.y;
                    }
                }
            }
        }
        __syncthreads();   // readers of As[buf] done; As[1-buf] fully written
    }

    // reduce across g (lane bits 2..4) so only tig lanes carry channel sums
    #pragma unroll
    for (int m = 4; m <= 16; m <<= 1) {
        #pragma unroll
        for (int nt = 0; nt < 4; nt++) {
            ps[nt][0] += __shfl_xor_sync(0xffffffffu, ps[nt][0], m);
            ps[nt][1] += __shfl_xor_sync(0xffffffffu, ps[nt][1], m);
            pq[nt][0] += __shfl_xor_sync(0xffffffffu, pq[nt][0], m);
            pq[nt][1] += __shfl_xor_sync(0xffffffffu, pq[nt][1], m);
        }
    }
    if (g == 0) {
        #pragma unroll
        for (int nt = 0; nt < 4; nt++) {
            int c = wn + nt * 8 + 2 * tig;
            atomicAdd(&bn_s[c],     ps[nt][0]);
            atomicAdd(&bn_s[c + 1], ps[nt][1]);
            atomicAdd(&bn_q[c],     pq[nt][0]);
            atomicAdd(&bn_q[c + 1], pq[nt][1]);
        }
    }
    __syncthreads();
    if (tid < C_OUT) {
        atomicAdd(&g_bn1_sum[tid], bn_s[tid]);
        atomicAdd(&g_bn1_sq[tid],  bn_q[tid]);
    }
}

// ---------------- K4: gather segment-sum (grid-stride warp loop, 2 groups/warp) ----------------
#define K4_GRP_PER_WARP 2
__global__ __launch_bounds__(128) void k4_segsum(
    const float* __restrict__ P,
    const float* __restrict__ Wp1, const float* __restrict__ bp1,
    const float* __restrict__ Wp2, const float* __restrict__ bp2,
    const float* __restrict__ g1,  const float* __restrict__ be1, int n)
{
    int tid = threadIdx.x, lane = tid & 31, w = tid >> 5;
    int warpId = blockIdx.x * 4 + w;
    int nwarp = gridDim.x * 4;

    const float4* W1 = (const float4*)Wp1;
    const float4* W2 = (const float4*)Wp2;
    float4 w10 = __ldg(W1 + lane),      w11 = __ldg(W1 + 32 + lane), w12 = __ldg(W1 + 64 + lane);
    float4 b1v = __ldg((const float4*)bp1 + lane);
    float4 w20 = __ldg(W2 + lane),      w21 = __ldg(W2 + 32 + lane), w22 = __ldg(W2 + 64 + lane);
    float4 b2v = __ldg((const float4*)bp2 + lane);
    float4 a1, bb1;
    bn_affine(g_bn1_sum, g_bn1_sq, g1, be1, lane * 4, 1.0f / (float)n, a1, bb1);

    float4 accS = f4zero(), accQ = f4zero();   // BN2 sum / sumsq partials

    for (int g = warpId; g < G_SEG; g += nwarp) {
        int beg = g_off[g];
        int cnt = g_hist[g];
        float4 s = f4zero(), tA = f4zero(), tQ = f4zero();

        int iA = (cnt > 0) ? __ldg(&g_order[beg]) : 0;
        for (int m = 0; m < cnt; m++) {
            int iB = (m + 1 < cnt) ? __ldg(&g_order[beg + m + 1]) : 0;
            float px = floorf(__ldg(P + 3*iA));
            float py = floorf(__ldg(P + 3*iA + 1));
            float pz = floorf(__ldg(P + 3*iA + 2));
            float4 y = ldy4(g_y + (size_t)iA * C_OUT + lane*4);   // keep L2-resident for k5
            float4 feat = f4fma(y, a1, bb1);
            float4 pw1 = f4sfma(px, w10, f4sfma(py, w11, f4sfma(pz, w12, b1v)));
            float4 pw2 = f4sfma(px, w20, f4sfma(py, w21, f4sfma(pz, w22, b2v)));
            float4 a = f4mul(pw2, feat);
            s  = f4fma(pw1, feat, s);
            tA = f4add(tA, a);
            tQ = f4fma(a, a, tQ);
            iA = iB;
        }
        *(float4*)(g_seg + (size_t)g * C_OUT + lane*4) = s;

        float c = (float)cnt;
        accS = f4add(accS, f4sub(tA, f4smul(c, s)));
        float4 q = f4sub(tQ, f4smul(2.f, f4mul(s, tA)));
        q = f4fma(s, f4smul(c, s), q);
        accQ = f4add(accQ, q);
    }

    __shared__ float rs[512], rq[512];
    rs[w*128 + lane*4 + 0] = accS.x; rq[w*128 + lane*4 + 0] = accQ.x;
    rs[w*128 + lane*4 + 1] = accS.y; rq[w*128 + lane*4 + 1] = accQ.y;
    rs[w*128 + lane*4 + 2] = accS.z; rq[w*128 + lane*4 + 2] = accQ.z;
    rs[w*128 + lane*4 + 3] = accS.w; rq[w*128 + lane*4 + 3] = accQ.w;
    __syncthreads();
    if (tid < 128) {
        float s = 0.f, q = 0.f;
        #pragma unroll
        for (int t = 0; t < 4; t++) { s += rs[t*128 + tid]; q += rq[t*128 + tid]; }
        atomicAdd(&g_bn2_sum[tid], s);
        atomicAdd(&g_bn2_sq[tid], q);
    }
}

// ---------------- K5: final output (grid-stride warp loop; streaming hints) ----------------
__global__ __launch_bounds__(256) void k5_out(
    const float* __restrict__ P, const int* __restrict__ unq,
    const float* __restrict__ Wp2, const float* __restrict__ bp2,
    const float* __restrict__ g1,  const float* __restrict__ be1,
    const float* __restrict__ g2,  const float* __restrict__ be2,
    float* __restrict__ Out, int n)
{
    int lane = threadIdx.x & 31;
    int warpId = (blockIdx.x * blockDim.x + threadIdx.x) >> 5;
    int nwarp = (gridDim.x * blockDim.x) >> 5;

    float inv_n = 1.0f / (float)n;
    float4 a1, bb1, a2, bb2;
    bn_affine(g_bn1_sum, g_bn1_sq, g1, be1, lane * 4, inv_n, a1, bb1);
    bn_affine(g_bn2_sum, g_bn2_sq, g2, be2, lane * 4, inv_n, a2, bb2);
    const float4* W2 = (const float4*)Wp2;
    float4 w20 = __ldg(W2 + lane), w21 = __ldg(W2 + 32 + lane), w22 = __ldg(W2 + 64 + lane);
    float4 b2v = __ldg((const float4*)bp2 + lane);

    for (int i = warpId; i < n; i += nwarp) {
        int g = __ldg(unq + i);
        float px = floorf(__ldg(P + 3*i));
        float py = floorf(__ldg(P + 3*i + 1));
        float pz = floorf(__ldg(P + 3*i + 2));
        float4 y  = ldy4_cs(g_y + (size_t)i * C_OUT + lane*4);          // last read: evict-first
        float4 sv = *(const float4*)(g_seg + (size_t)g * C_OUT + lane*4); // keep L2-resident
        float4 feat = f4fma(y, a1, bb1);
        float4 pw2 = f4sfma(px, w20, f4sfma(py, w21, f4sfma(pz, w22, b2v)));
        float4 o = f4sub(f4mul(pw2, feat), sv);
        o = f4fma(o, a2, bb2);
        o.x = fmaxf(o.x, 0.f); o.y = fmaxf(o.y, 0.f);
        o.z = fmaxf(o.z, 0.f); o.w = fmaxf(o.w, 0.f);
        __stcs((float4*)(Out + (size_t)i * C_OUT + lane*4), o);          // evict-first store
    }
}

// ---------------- launch ----------------
extern "C" void kernel_launch(void* const* d_in, const int* in_sizes, int n_in,
                              void* d_out, int out_size)
{
    const float* P    = (const float*)d_in[0];   // points_xyz [N,3]
    const float* X    = (const float*)d_in[1];   // feat_all  [N,64]
    const int*   unq  = (const int*)  d_in[2];   // unq_inv   [N]
    const float* Wpre = (const float*)d_in[3];   // [64,128]
    const float* bpre = (const float*)d_in[4];
    const float* g1   = (const float*)d_in[5];
    const float* be1  = (const float*)d_in[6];
    const float* Wp1  = (const float*)d_in[7];   // [3,128]
    const float* bp1  = (const float*)d_in[8];
    const float* Wp2  = (const float*)d_in[9];   // [3,128]
    const float* bp2  = (const float*)d_in[10];
    const float* g2   = (const float*)d_in[11];
    const float* be2  = (const float*)d_in[12];
    float* Out = (float*)d_out;

    int N = in_sizes[2];

    // fork/join: CSR chain overlaps with k1 GEMM.
    cudaStream_t s2;
    cudaEvent_t evFork, evJoin;
    cudaStreamCreateWithFlags(&s2, cudaStreamNonBlocking);
    cudaEventCreateWithFlags(&evFork, cudaEventDisableTiming);
    cudaEventCreateWithFlags(&evJoin, cudaEventDisableTiming);

    k_init<<<(G_SEG + 255) / 256, 256>>>(Wpre);
    cudaEventRecord(evFork, 0);
    cudaStreamWaitEvent(s2, evFork, 0);

    // stream B: CSR chain (only depends on unq + init)
    k_hist<<<(N + 255) / 256, 256, 0, s2>>>(unq, N);
    k_offsets<<<(G_SEG + 255) / 256, 256, 0, s2>>>();
    k_scatter<<<(N + 255) / 256, 256, 0, s2>>>(unq, N);
    cudaEventRecord(evJoin, s2);

    // stream A (default): GEMM concurrent with CSR chain (4 tiles/block, double-buffered)
    int rowsPerBlock = 64 * K1_TILES;
    k1_mma<<<(N + rowsPerBlock - 1) / rowsPerBlock, 256>>>(X, bpre, N);

    cudaStreamWaitEvent(0, evJoin, 0);
    k4_segsum<<<G_SEG / (4 * K4_GRP_PER_WARP), 128>>>(P, Wp1, bp1, Wp2, bp2, g1, be1, N);
    k5_out<<<1024, 256>>>(P, unq, Wp2, bp2, g1, be1, g2, be2, Out, N);

    cudaStreamDestroy(s2);
    cudaEventDestroy(evFork);
    cudaEventDestroy(evJoin);
}